// round 15
// baseline (speedup 1.0000x reference)
#include <cuda_runtime.h>
#include <cuda_bf16.h>
#include <math.h>

// Problem dims
#define BB   2
#define NN   256
#define ND   128
#define ED   256
#define HIDD 256
#define NH   8
#define DH   32
#define LN_EPS 1e-5f

// ---------------- device scratch ----------------
__device__ float g_h   [BB*NN*HIDD];
__device__ float g_q   [BB*NN*HIDD];
__device__ float g_k   [BB*NN*HIDD];
__device__ float g_v   [BB*NN*HIDD];
__device__ float g_scores[BB*NH*NN*NN];   // attention probabilities
__device__ float g_eattn [BB*NH*NN*NN];
__device__ float g_amean [BB*NN*NN];
__device__ float g_ao  [BB*NN*HIDD];
__device__ float g_tmp [BB*NN*HIDD];
__device__ float g_P   [BB*NN*ED];
// bf16x2 of [Wep|Weg], fragment-ordered for the head-group-split edge kernel:
// o = ((((((c*2+hg)*8+cw)*2+step)*2+q)*32)+lane)*4+pos
// reg=q*4+pos, nt=reg>>1, half=reg&1, g=lane>>2, tig=lane&3
// k pair = c*32 + step*16 + tig*2 + half*8 (+1)
// cw<4:  n = hg*128 + cw*32 + nt*8 + g        (from Wep)
// cw>=4: n = hg*128 + (cw-4)*32 + nt*8 + g    (from Weg)
__device__ unsigned g_Wc[65536];

// ---------------- helpers ----------------
__device__ __forceinline__ float warpSum(float v) {
    #pragma unroll
    for (int o = 16; o; o >>= 1) v += __shfl_xor_sync(0xffffffffu, v, o);
    return v;
}
__device__ __forceinline__ unsigned pack_bf16(float lo, float hi) {
    __nv_bfloat162 p = __floats2bfloat162_rn(lo, hi);
    return *(unsigned*)&p;
}
__device__ __forceinline__ void mma_bf16(float* d, const unsigned* a, unsigned b0, unsigned b1) {
    asm volatile("mma.sync.aligned.m16n8k16.row.col.f32.bf16.bf16.f32 "
        "{%0,%1,%2,%3}, {%4,%5,%6,%7}, {%8,%9}, {%0,%1,%2,%3};"
        : "+f"(d[0]), "+f"(d[1]), "+f"(d[2]), "+f"(d[3])
        : "r"(a[0]), "r"(a[1]), "r"(a[2]), "r"(a[3]), "r"(b0), "r"(b1));
}
__device__ __forceinline__ void cp_async16(void* smem, const void* gmem) {
    unsigned saddr = (unsigned)__cvta_generic_to_shared(smem);
    asm volatile("cp.async.cg.shared.global [%0], [%1], 16;" :: "r"(saddr), "l"(gmem));
}
#define CP_COMMIT() asm volatile("cp.async.commit_group;")
#define CP_WAIT0()  asm volatile("cp.async.wait_group 0;")

// ---------------- weight pre-convert into fragment-ordered bf16 ----------------
__global__ __launch_bounds__(256)
void cvt_w_kernel(const float* __restrict__ Wep, const float* __restrict__ Weg)
{
    int o = blockIdx.x * 256 + threadIdx.x;   // 0..65535
    int pos  = o & 3;
    int lane = (o >> 2) & 31;
    int q    = (o >> 7) & 1;
    int step = (o >> 8) & 1;
    int cw   = (o >> 9) & 7;
    int hg   = (o >> 12) & 1;
    int c    = o >> 13;
    int reg = q*4 + pos, nt = reg >> 1, half = reg & 1;
    int g = lane >> 2, tig = lane & 3;
    int k = c*32 + step*16 + tig*2 + half*8;
    int n;
    const float* W;
    if (cw < 4) { n = hg*128 + cw*32 + nt*8 + g;        W = Wep; }
    else        { n = hg*128 + (cw-4)*32 + nt*8 + g;    W = Weg; }
    g_Wc[o] = pack_bf16(W[k*256 + n], W[(k+1)*256 + n]);
}

// ---------------- edge projection + gate + head reduction (bf16 MMA) ----------------
// CTA (rb, hg): 64 E-rows x 256 cols (P half + G half of 4 heads), 512 threads,
// 8 chunks of k32, double buffered. 2 CTAs/SM.
#define EAW 20
#define EA0 0
#define EA1 5120
#define EB0 10240
#define EB1 26624
#define EDGE_SMEM 43008    // mainloop 43008 B; Gs epilogue reuses 36864 B

__global__ __launch_bounds__(512, 2)
void edge_attn_mma_kernel(const float* __restrict__ E,
                          const float* __restrict__ bep, const float* __restrict__ beg)
{
    extern __shared__ float sm[];
    char* smc = (char*)sm;
    __shared__ float sbep[256], sbeg[256];

    int tid  = threadIdx.x;
    int lane = tid & 31, w = tid >> 5;
    int g    = lane >> 2, tig = lane & 3;
    int rh   = w >> 3;                   // row half (0/1)
    int cw   = w & 7;                    // 0-3: P warps, 4-7: G warps
    int hg   = blockIdx.y;               // head group (0/1)
    size_t i0 = (size_t)blockIdx.x * 64;

    if (tid < 256) { sbep[tid] = bep[tid]; sbeg[tid] = beg[tid]; }

    float acc[2][4][4];
    #pragma unroll
    for (int mi = 0; mi < 2; mi++)
        #pragma unroll
        for (int nt = 0; nt < 4; nt++)
            #pragma unroll
            for (int q = 0; q < 4; q++) acc[mi][nt][q] = 0.f;

    // each thread owns one float4 (4 consecutive k) of the A tile per chunk
    int tr = tid >> 3, kq = tid & 7;
    const float* asrc = E + (i0 + tr)*256 + kq*4;
    unsigned aoff = (unsigned)(tr*EAW + kq*2);     // b32 word offset
    const unsigned* wbase = g_Wc + hg*4096;        // + c*8192 per chunk

    // prologue: chunk 0
    {
        float4 av = *(const float4*)(asrc);
        unsigned* Ad = (unsigned*)(smc + EA0);
        uint2 wv = { pack_bf16(av.x, av.y), pack_bf16(av.z, av.w) };
        *(uint2*)(Ad + aoff) = wv;
        #pragma unroll
        for (int t = 0; t < 2; t++) {
            int idx = tid + t*512;                 // 1024 float4 = 16KB
            cp_async16(smc + EB0 + idx*16, wbase + idx*4);
        }
        CP_COMMIT();
    }

    #pragma unroll 1
    for (int c = 0; c < 8; c++) {
        CP_WAIT0();
        __syncthreads();                      // chunk c resident in buf[c&1]

        float4 a_pre;
        if (c < 7) {
            a_pre = *(const float4*)(asrc + (c + 1)*32);       // LDG early, hidden by MMAs
            char* Bb = smc + (((c + 1) & 1) ? EB1 : EB0);
            const unsigned* bsrc = wbase + (size_t)(c + 1)*8192;
            #pragma unroll
            for (int t = 0; t < 2; t++) {
                int idx = tid + t*512;
                cp_async16(Bb + idx*16, bsrc + idx*4);
            }
            CP_COMMIT();
        }

        const unsigned* Au = (const unsigned*)(smc + ((c & 1) ? EA1 : EA0));
        const unsigned* Bu = (const unsigned*)(smc + ((c & 1) ? EB1 : EB0));
        #pragma unroll
        for (int step = 0; step < 2; step++) {
            unsigned a[2][4];
            #pragma unroll
            for (int mi = 0; mi < 2; mi++) {
                int r = rh*32 + mi*16 + g;
                a[mi][0] = Au[r*EAW + step*8 + tig];
                a[mi][1] = Au[(r+8)*EAW + step*8 + tig];
                a[mi][2] = Au[r*EAW + step*8 + tig + 4];
                a[mi][3] = Au[(r+8)*EAW + step*8 + tig + 4];
            }
            unsigned br[8];
            const uint4* bs = (const uint4*)Bu + ((cw*2 + step) << 6);
            *(uint4*)(br + 0) = bs[lane];
            *(uint4*)(br + 4) = bs[32 + lane];
            #pragma unroll
            for (int nt = 0; nt < 4; nt++) {
                mma_bf16(acc[0][nt], a[0], br[2*nt], br[2*nt + 1]);
                mma_bf16(acc[1][nt], a[1], br[2*nt], br[2*nt + 1]);
            }
        }

        if (c < 7) {                          // STS of prefetched A after MMAs
            unsigned* Ad = (unsigned*)(smc + (((c + 1) & 1) ? EA1 : EA0));
            uint2 wv = { pack_bf16(a_pre.x, a_pre.y), pack_bf16(a_pre.z, a_pre.w) };
            *(uint2*)(Ad + aoff) = wv;
        }
        __syncthreads();
    }

    // ---- epilogue: G warps stage sigmoid(G+beg) in fragment order ----
    // Gs[gw][lane][v], v = (mi*4+nt)*4+q, lane stride 36 (conflict-free)
    float* Gs = sm;
    if (cw >= 4) {
        int gw = rh*4 + (cw - 4);
        float* dst = Gs + gw*1152 + lane*36;
        int cb0 = hg*128 + (cw - 4)*32;
        #pragma unroll
        for (int mi = 0; mi < 2; mi++)
            #pragma unroll
            for (int nt = 0; nt < 4; nt++) {
                int cc = cb0 + nt*8 + tig*2;
                float b0 = sbeg[cc], b1 = sbeg[cc + 1];
                float4 v;
                v.x = 1.f / (1.f + __expf(-(acc[mi][nt][0] + b0)));
                v.y = 1.f / (1.f + __expf(-(acc[mi][nt][1] + b1)));
                v.z = 1.f / (1.f + __expf(-(acc[mi][nt][2] + b0)));
                v.w = 1.f / (1.f + __expf(-(acc[mi][nt][3] + b1)));
                *(float4*)(dst + (mi*4 + nt)*4) = v;
            }
    }
    __syncthreads();

    // ---- P warps: gated product + tig-group reduction + scatter ----
    if (cw < 4) {
        int head = hg*4 + cw;
        const float* src = Gs + (rh*4 + cw)*1152 + lane*36;
        int cb0 = hg*128 + cw*32;
        float s[4] = {0.f, 0.f, 0.f, 0.f};     // [mi*2 + rowhalf]
        #pragma unroll
        for (int mi = 0; mi < 2; mi++)
            #pragma unroll
            for (int nt = 0; nt < 4; nt++) {
                int cc = cb0 + nt*8 + tig*2;
                float b0 = sbep[cc], b1 = sbep[cc + 1];
                float4 gv = *(const float4*)(src + (mi*4 + nt)*4);
                s[mi*2+0] += (acc[mi][nt][0] + b0)*gv.x + (acc[mi][nt][1] + b1)*gv.y;
                s[mi*2+1] += (acc[mi][nt][2] + b0)*gv.z + (acc[mi][nt][3] + b1)*gv.w;
            }
        #pragma unroll
        for (int o = 1; o < 4; o <<= 1) {
            #pragma unroll
            for (int j = 0; j < 4; j++) s[j] += __shfl_xor_sync(0xffffffffu, s[j], o);
        }
        if (tig == 0) {
            #pragma unroll
            for (int mi = 0; mi < 2; mi++)
                #pragma unroll
                for (int rr = 0; rr < 2; rr++) {
                    int r = rh*32 + mi*16 + g + rr*8;
                    size_t i = i0 + r;
                    int m = (int)(i & 255), n = (int)((i >> 8) & 255), b = (int)(i >> 16);
                    g_eattn[(((size_t)(b*NH + head)*NN + n)*NN) + m] = s[mi*2 + rr];
                }
        }
    }
}

// ---------------- fused attention: scores + bias + mask + softmax + attn@V ----------------
#define AKS 264
#define AVS 36
#define AQS 33
#define ATT_SMEM ((32*AKS + 256*AVS + 32*AQS + 32*AKS) * 4)

__global__ __launch_bounds__(256, 1)
void attention_kernel(const int* __restrict__ adj)
{
    extern __shared__ float smf[];
    float* Kt = smf;
    float* Vs = Kt + 32*AKS;
    float* Qs = Vs + 256*AVS;
    float* Ps = Qs + 32*AQS;

    int bid = blockIdx.x;
    int nb = bid & 7, h = (bid >> 3) & 7, b = bid >> 6;
    int n0 = nb * 32;
    int tid = threadIdx.x;

    const float* kbase = g_k + (size_t)(b*NN)*HIDD + h*DH;
    const float* vbase = g_v + (size_t)(b*NN)*HIDD + h*DH;
    #pragma unroll
    for (int it = 0; it < 32; it++) {
        int idx = tid + it*256;
        int m = idx >> 5, d = idx & 31;
        float kv = kbase[(size_t)m*HIDD + d];
        float vv = vbase[(size_t)m*HIDD + d];
        Kt[d*AKS + m] = kv;
        Vs[m*AVS + d] = vv;
    }
    #pragma unroll
    for (int it = 0; it < 4; it++) {
        int idx = tid + it*256;
        int r = idx >> 5, d = idx & 31;
        Qs[r*AQS + d] = g_q[(size_t)(b*NN + n0 + r)*HIDD + h*DH + d];
    }
    __syncthreads();

    int r = tid >> 3, cg = tid & 7;

    float acc[8][4];
    #pragma unroll
    for (int c = 0; c < 8; c++)
        #pragma unroll
        for (int j = 0; j < 4; j++) acc[c][j] = 0.f;

    #pragma unroll
    for (int d = 0; d < 32; d++) {
        float qd = Qs[r*AQS + d];
        const float* krow = Kt + d*AKS + cg*4;
        #pragma unroll
        for (int c = 0; c < 8; c++) {
            float4 kv = *(const float4*)(krow + c*32);
            acc[c][0] = fmaf(qd, kv.x, acc[c][0]);
            acc[c][1] = fmaf(qd, kv.y, acc[c][1]);
            acc[c][2] = fmaf(qd, kv.z, acc[c][2]);
            acc[c][3] = fmaf(qd, kv.w, acc[c][3]);
        }
    }

    size_t rowbase = ((size_t)(b*NH + h)*NN + (n0 + r)) * NN;
    const float* erow = g_eattn + rowbase;
    const int*   arow = adj + (size_t)(b*NN + n0 + r)*NN;

    const float scale = 0.17677669529663687f;
    float mx = -1e30f;
    #pragma unroll
    for (int c = 0; c < 8; c++) {
        int m0 = cg*4 + c*32;
        float4 ev = *(const float4*)(erow + m0);
        int4   av = *(const int4*)(arow + m0);
        acc[c][0] = (av.x == 0) ? -1e9f : fmaf(acc[c][0], scale, ev.x);
        acc[c][1] = (av.y == 0) ? -1e9f : fmaf(acc[c][1], scale, ev.y);
        acc[c][2] = (av.z == 0) ? -1e9f : fmaf(acc[c][2], scale, ev.z);
        acc[c][3] = (av.w == 0) ? -1e9f : fmaf(acc[c][3], scale, ev.w);
        #pragma unroll
        for (int j = 0; j < 4; j++) mx = fmaxf(mx, acc[c][j]);
    }
    #pragma unroll
    for (int o = 1; o < 8; o <<= 1) mx = fmaxf(mx, __shfl_xor_sync(0xffffffffu, mx, o));

    float sum = 0.f;
    #pragma unroll
    for (int c = 0; c < 8; c++)
        #pragma unroll
        for (int j = 0; j < 4; j++) {
            acc[c][j] = __expf(acc[c][j] - mx);
            sum += acc[c][j];
        }
    #pragma unroll
    for (int o = 1; o < 8; o <<= 1) sum += __shfl_xor_sync(0xffffffffu, sum, o);
    float inv = 1.f / sum;

    float* psrow = Ps + r*AKS;
    float* grow  = g_scores + rowbase;
    #pragma unroll
    for (int c = 0; c < 8; c++) {
        int m0 = cg*4 + c*32;
        float4 p;
        p.x = acc[c][0] * inv; p.y = acc[c][1] * inv;
        p.z = acc[c][2] * inv; p.w = acc[c][3] * inv;
        *(float4*)(psrow + m0) = p;
        *(float4*)(grow + m0)  = p;
    }
    __syncwarp();

    float o0 = 0.f, o1 = 0.f, o2 = 0.f, o3 = 0.f;
    #pragma unroll 8
    for (int m = 0; m < 256; m++) {
        float p = psrow[m];
        float4 vv = *(const float4*)(Vs + m*AVS + cg*4);
        o0 = fmaf(p, vv.x, o0);
        o1 = fmaf(p, vv.y, o1);
        o2 = fmaf(p, vv.z, o2);
        o3 = fmaf(p, vv.w, o3);
    }
    float4 ov = {o0, o1, o2, o3};
    *(float4*)(g_ao + (size_t)(b*NN + n0 + r)*HIDD + h*DH + cg*4) = ov;
}

// ---------------- generic fp32 GEMM body: 32x64 tile, BK=32 ----------------
__device__ __forceinline__ void gemm_body(const float* __restrict__ A, const float* __restrict__ W,
                                          const float* __restrict__ bias, float* __restrict__ C,
                                          int M, int Nc, int K, int bx, int by)
{
    __shared__ float As[32][33];
    __shared__ float Ws[32][64];
    int tid = threadIdx.x;
    int r0 = by * 32, c0 = bx * 64;
    int ty = tid >> 4, tx = tid & 15;
    float acc[2][4] = {};

    for (int kc = 0; kc < K; kc += 32) {
        {
            int r = tid >> 3, c4 = tid & 7;
            float4 v = *(const float4*)(A + (size_t)(r0 + r)*K + kc + c4*4);
            As[c4*4+0][r] = v.x; As[c4*4+1][r] = v.y;
            As[c4*4+2][r] = v.z; As[c4*4+3][r] = v.w;
        }
        #pragma unroll
        for (int it = 0; it < 2; it++) {
            int j = tid + it*256;
            int rr = j >> 4, c4 = j & 15;
            *(float4*)(&Ws[rr][c4*4]) = *(const float4*)(W + (size_t)(kc + rr)*Nc + c0 + c4*4);
        }
        __syncthreads();
        #pragma unroll
        for (int k = 0; k < 32; k++) {
            float a0 = As[k][ty*2], a1 = As[k][ty*2+1];
            float4 bv = *(float4*)(&Ws[k][tx*4]);
            acc[0][0] = fmaf(a0, bv.x, acc[0][0]);
            acc[0][1] = fmaf(a0, bv.y, acc[0][1]);
            acc[0][2] = fmaf(a0, bv.z, acc[0][2]);
            acc[0][3] = fmaf(a0, bv.w, acc[0][3]);
            acc[1][0] = fmaf(a1, bv.x, acc[1][0]);
            acc[1][1] = fmaf(a1, bv.y, acc[1][1]);
            acc[1][2] = fmaf(a1, bv.z, acc[1][2]);
            acc[1][3] = fmaf(a1, bv.w, acc[1][3]);
        }
        __syncthreads();
    }
    #pragma unroll
    for (int i = 0; i < 2; i++)
        #pragma unroll
        for (int j = 0; j < 4; j++) {
            int cc = c0 + tx*4 + j;
            float v = acc[i][j];
            if (bias) v += bias[cc];
            C[(size_t)(r0 + ty*2 + i)*Nc + cc] = v;
        }
}

__global__ __launch_bounds__(256)
void gemm_one_kernel(const float* __restrict__ A, const float* __restrict__ W,
                     const float* __restrict__ bias, float* __restrict__ C,
                     int M, int Nc, int K)
{
    gemm_body(A, W, bias, C, M, Nc, K, blockIdx.x, blockIdx.y);
}

__global__ __launch_bounds__(256)
void gemm_qkv_kernel(const float* __restrict__ A,
                     const float* __restrict__ Wq, const float* __restrict__ bq,
                     const float* __restrict__ Wk, const float* __restrict__ bk,
                     const float* __restrict__ Wv, const float* __restrict__ bv,
                     float* __restrict__ oq, float* __restrict__ ok, float* __restrict__ ov)
{
    int z = blockIdx.z;
    const float* W = (z == 0) ? Wq : (z == 1) ? Wk : Wv;
    const float* bb = (z == 0) ? bq : (z == 1) ? bk : bv;
    float* C = (z == 0) ? oq : (z == 1) ? ok : ov;
    gemm_body(A, W, bb, C, 512, 256, 256, blockIdx.x, blockIdx.y);
}

// ---------------- attn mean over heads ----------------
__global__ __launch_bounds__(256)
void attn_mean_kernel()
{
    int j = blockIdx.x * 256 + threadIdx.x;
    int b = j >> 16, nm = j & 65535;
    float s = 0.f;
    #pragma unroll
    for (int h = 0; h < NH; h++) s += g_scores[(((size_t)(b*NH + h)) << 16) + nm];
    g_amean[j] = s * 0.125f;
}

// ---------------- h_out = LN(residual + o)  (warp per row) ----------------
__global__ __launch_bounds__(256)
void ln_node_kernel(const float* __restrict__ g1, const float* __restrict__ b1,
                    float* __restrict__ out)
{
    int row = blockIdx.x * 8 + (threadIdx.x >> 5);
    int lane = threadIdx.x & 31;
    const float* ha = g_h + (size_t)row*256;
    const float* ta = g_tmp + (size_t)row*256;
    float4 a0 = *(const float4*)(ha + lane*4);
    float4 t0 = *(const float4*)(ta + lane*4);
    float4 a1 = *(const float4*)(ha + 128 + lane*4);
    float4 t1 = *(const float4*)(ta + 128 + lane*4);
    float x[8] = {a0.x+t0.x, a0.y+t0.y, a0.z+t0.z, a0.w+t0.w,
                  a1.x+t1.x, a1.y+t1.y, a1.z+t1.z, a1.w+t1.w};
    float s = 0.f;
    #pragma unroll
    for (int j = 0; j < 8; j++) s += x[j];
    float mean = warpSum(s) * (1.f/256.f);
    float vs = 0.f;
    #pragma unroll
    for (int j = 0; j < 8; j++) { float d = x[j] - mean; vs += d*d; }
    float inv = rsqrtf(warpSum(vs) * (1.f/256.f) + LN_EPS);
    float* o = out + (size_t)row*256;
    #pragma unroll
    for (int j = 0; j < 8; j++) {
        int c = (j < 4) ? (lane*4 + j) : (128 + lane*4 + j - 4);
        o[c] = (x[j] - mean) * inv * g1[c] + b1[c];
    }
}

// ---------------- edge_out = LN(E + amean*0.5*(P_n + P_m) + beo)  (warp per row) ----------------
__global__ __launch_bounds__(256)
void edge_out_kernel(const float* __restrict__ E, const float* __restrict__ beo,
                     const float* __restrict__ g2, const float* __restrict__ b2,
                     float* __restrict__ out)
{
    size_t i = (size_t)blockIdx.x * 8 + (threadIdx.x >> 5);
    int lane = threadIdx.x & 31;
    int m = (int)(i & 255), n = (int)((i >> 8) & 255), b = (int)(i >> 16);
    float am = g_amean[i] * 0.5f;
    const float* Er = E + i*256;
    const float* Pn = g_P + (size_t)(b*NN + n)*256;
    const float* Pm = g_P + (size_t)(b*NN + m)*256;

    float x[8];
    #pragma unroll
    for (int half = 0; half < 2; half++) {
        int c = half*128 + lane*4;
        float4 e  = *(const float4*)(Er + c);
        float4 pn = *(const float4*)(Pn + c);
        float4 pm = *(const float4*)(Pm + c);
        float4 bo = *(const float4*)(beo + c);
        x[half*4+0] = e.x + am*(pn.x + pm.x) + bo.x;
        x[half*4+1] = e.y + am*(pn.y + pm.y) + bo.y;
        x[half*4+2] = e.z + am*(pn.z + pm.z) + bo.z;
        x[half*4+3] = e.w + am*(pn.w + pm.w) + bo.w;
    }
    float s = 0.f;
    #pragma unroll
    for (int j = 0; j < 8; j++) s += x[j];
    float mean = warpSum(s) * (1.f/256.f);
    float vs = 0.f;
    #pragma unroll
    for (int j = 0; j < 8; j++) { float d = x[j] - mean; vs += d*d; }
    float inv = rsqrtf(warpSum(vs) * (1.f/256.f) + LN_EPS);
    float* o = out + i*256;
    #pragma unroll
    for (int half = 0; half < 2; half++) {
        int c = half*128 + lane*4;
        float4 gg = *(const float4*)(g2 + c);
        float4 bb = *(const float4*)(b2 + c);
        float4 r;
        r.x = (x[half*4+0] - mean) * inv * gg.x + bb.x;
        r.y = (x[half*4+1] - mean) * inv * gg.y + bb.y;
        r.z = (x[half*4+2] - mean) * inv * gg.z + bb.z;
        r.w = (x[half*4+3] - mean) * inv * gg.w + bb.w;
        *(float4*)(o + c) = r;
    }
}

// ---------------- launch ----------------
extern "C" void kernel_launch(void* const* d_in, const int* in_sizes, int n_in,
                              void* d_out, int out_size)
{
    const float* node = (const float*)d_in[0];
    const float* edge = (const float*)d_in[1];
    const int*   adj  = (const int*)  d_in[2];
    const float* Wn  = (const float*)d_in[3];  const float* bn  = (const float*)d_in[4];
    const float* Wq  = (const float*)d_in[5];  const float* bq  = (const float*)d_in[6];
    const float* Wk  = (const float*)d_in[7];  const float* bk  = (const float*)d_in[8];
    const float* Wv  = (const float*)d_in[9];  const float* bv  = (const float*)d_in[10];
    const float* Wep = (const float*)d_in[11]; const float* bep = (const float*)d_in[12];
    const float* Weg = (const float*)d_in[13]; const float* beg = (const float*)d_in[14];
    const float* Wo  = (const float*)d_in[15]; const float* bo  = (const float*)d_in[16];
    const float* Weo = (const float*)d_in[17]; const float* beo = (const float*)d_in[18];
    const float* g1  = (const float*)d_in[19]; const float* b1  = (const float*)d_in[20];
    const float* g2  = (const float*)d_in[21]; const float* b2  = (const float*)d_in[22];

    float* out   = (float*)d_out;
    float* h_out = out;
    float* e_out = out + (size_t)BB*NN*HIDD;

    float *ph, *pq, *pk, *pv, *pao, *ptmp, *pP;
    cudaGetSymbolAddress((void**)&ph,   g_h);
    cudaGetSymbolAddress((void**)&pq,   g_q);
    cudaGetSymbolAddress((void**)&pk,   g_k);
    cudaGetSymbolAddress((void**)&pv,   g_v);
    cudaGetSymbolAddress((void**)&pao,  g_ao);
    cudaGetSymbolAddress((void**)&ptmp, g_tmp);
    cudaGetSymbolAddress((void**)&pP,   g_P);

    cudaFuncSetAttribute(edge_attn_mma_kernel,
                         cudaFuncAttributeMaxDynamicSharedMemorySize, EDGE_SMEM);
    cudaFuncSetAttribute(attention_kernel,
                         cudaFuncAttributeMaxDynamicSharedMemorySize, ATT_SMEM);

    // weight convert/permute (independent) + node projection
    cvt_w_kernel<<<256, 256>>>(Wep, Weg);
    gemm_one_kernel<<<dim3(4, 16), 256>>>(node, Wn, bn, ph, 512, 256, 128);

    // QKV in one launch
    gemm_qkv_kernel<<<dim3(4, 16, 3), 256>>>(ph, Wq, bq, Wk, bk, Wv, bv, pq, pk, pv);

    // edge bias (tensor cores, head-group split), then fused attention
    edge_attn_mma_kernel<<<dim3((BB*NN*NN)/64, 2), 512, EDGE_SMEM>>>(edge, bep, beg);
    attention_kernel<<<BB*NH*8, 256, ATT_SMEM>>>(adj);

    // mean over heads (for edge update)
    attn_mean_kernel<<<(BB*NN*NN)/256, 256>>>();

    // out-proj + node LN
    gemm_one_kernel<<<dim3(4, 16), 256>>>(pao, Wo, bo, ptmp, 512, 256, 256);
    ln_node_kernel<<<(BB*NN)/8, 256>>>(g1, b1, h_out);

    // P = h_out @ Weo, then fused edge output LN
    gemm_one_kernel<<<dim3(4, 16), 256>>>(h_out, Weo, (const float*)nullptr, pP, 512, 256, 256);
    edge_out_kernel<<<(BB*NN*NN)/8, 256>>>(edge, beo, g2, b2, e_out);
}

// round 17
// speedup vs baseline: 1.3997x; 1.3997x over previous
#include <cuda_runtime.h>
#include <cuda_bf16.h>
#include <math.h>

// Problem dims
#define BB   2
#define NN   256
#define ND   128
#define ED   256
#define HIDD 256
#define NH   8
#define DH   32
#define LN_EPS 1e-5f

// ---------------- device scratch ----------------
__device__ float g_h   [BB*NN*HIDD];
__device__ float g_q   [BB*NN*HIDD];
__device__ float g_k   [BB*NN*HIDD];
__device__ float g_v   [BB*NN*HIDD];
__device__ float g_scores[BB*NH*NN*NN];   // attention probabilities
__device__ float g_eattn [BB*NH*NN*NN];
__device__ float g_amean [BB*NN*NN];
__device__ float g_ao  [BB*NN*HIDD];
__device__ float g_tmp [BB*NN*HIDD];
__device__ float g_P   [BB*NN*ED];
// bf16x2 of [Wep|Weg], fragment-ordered (identical to round-15 mapping):
// o = ((((((c*2+hg)*8+cw)*2+step)*2+q)*32)+lane)*4+pos
__device__ unsigned g_Wc[65536];
// bf16x2 of E, plain row-major pairs: word j = pack(E[2j], E[2j+1]); 128 words/row
__device__ unsigned g_Ec[16777216];

// ---------------- helpers ----------------
__device__ __forceinline__ float warpSum(float v) {
    #pragma unroll
    for (int o = 16; o; o >>= 1) v += __shfl_xor_sync(0xffffffffu, v, o);
    return v;
}
__device__ __forceinline__ unsigned pack_bf16(float lo, float hi) {
    __nv_bfloat162 p = __floats2bfloat162_rn(lo, hi);
    return *(unsigned*)&p;
}
__device__ __forceinline__ void mma_bf16(float* d, const unsigned* a, unsigned b0, unsigned b1) {
    asm volatile("mma.sync.aligned.m16n8k16.row.col.f32.bf16.bf16.f32 "
        "{%0,%1,%2,%3}, {%4,%5,%6,%7}, {%8,%9}, {%0,%1,%2,%3};"
        : "+f"(d[0]), "+f"(d[1]), "+f"(d[2]), "+f"(d[3])
        : "r"(a[0]), "r"(a[1]), "r"(a[2]), "r"(a[3]), "r"(b0), "r"(b1));
}
__device__ __forceinline__ void cp_async16(void* smem, const void* gmem) {
    unsigned saddr = (unsigned)__cvta_generic_to_shared(smem);
    asm volatile("cp.async.cg.shared.global [%0], [%1], 16;" :: "r"(saddr), "l"(gmem));
}
#define CP_COMMIT() asm volatile("cp.async.commit_group;")
#define CP_WAIT0()  asm volatile("cp.async.wait_group 0;")
#define CP_WAIT1()  asm volatile("cp.async.wait_group 1;")

// ---------------- E pre-convert to bf16 (row-major pairs) ----------------
__global__ __launch_bounds__(256)
void cvt_e_kernel(const float* __restrict__ E)
{
    size_t j = (size_t)blockIdx.x * 256 + threadIdx.x;   // float4 index, 8388608 total
    float4 v = ((const float4*)E)[j];
    uint2 o = { pack_bf16(v.x, v.y), pack_bf16(v.z, v.w) };
    ((uint2*)g_Ec)[j] = o;
}

// ---------------- weight pre-convert into fragment-ordered bf16 ----------------
__global__ __launch_bounds__(256)
void cvt_w_kernel(const float* __restrict__ Wep, const float* __restrict__ Weg)
{
    int o = blockIdx.x * 256 + threadIdx.x;   // 0..65535
    int pos  = o & 3;
    int lane = (o >> 2) & 31;
    int q    = (o >> 7) & 1;
    int step = (o >> 8) & 1;
    int cw   = (o >> 9) & 7;
    int hg   = (o >> 12) & 1;
    int c    = o >> 13;
    int reg = q*4 + pos, nt = reg >> 1, half = reg & 1;
    int g = lane >> 2, tig = lane & 3;
    int k = c*32 + step*16 + tig*2 + half*8;
    int n;
    const float* W;
    if (cw < 4) { n = hg*128 + cw*32 + nt*8 + g;        W = Wep; }
    else        { n = hg*128 + (cw-4)*32 + nt*8 + g;    W = Weg; }
    g_Wc[o] = pack_bf16(W[k*256 + n], W[(k+1)*256 + n]);
}

// ---------------- edge projection + gate + head reduction (bf16 MMA) ----------------
// CTA (rb, hg): 64 E-rows x 256 cols, 512 threads, 8 chunks of k32,
// TRIPLE buffered cp.async (A from g_Ec, B from g_Wc), 1 sync per chunk, 2 CTAs/SM.
#define EAW 20                 // A row stride in b32 words (conflict-free)
#define EAB 5120               // A tile bytes (64*20*4)
#define EBB 16384              // B tile bytes
#define EBBASE 15360           // = 3*EAB
#define EDGE_SMEM 64512        // 3*EAB + 3*EBB

__global__ __launch_bounds__(512, 2)
void edge_attn_mma_kernel(const float* __restrict__ bep, const float* __restrict__ beg)
{
    extern __shared__ float sm[];
    char* smc = (char*)sm;
    __shared__ float sbep[256], sbeg[256];

    int tid  = threadIdx.x;
    int lane = tid & 31, w = tid >> 5;
    int g    = lane >> 2, tig = lane & 3;
    int rh   = w >> 3;                   // row half (0/1)
    int cw   = w & 7;                    // 0-3: P warps, 4-7: G warps
    int hg   = blockIdx.y;               // head group (0/1)
    size_t i0 = (size_t)blockIdx.x * 64;

    if (tid < 256) { sbep[tid] = bep[tid]; sbeg[tid] = beg[tid]; }

    float acc[2][4][4];
    #pragma unroll
    for (int mi = 0; mi < 2; mi++)
        #pragma unroll
        for (int nt = 0; nt < 4; nt++)
            #pragma unroll
            for (int q = 0; q < 4; q++) acc[mi][nt][q] = 0.f;

    const unsigned* wbase = g_Wc + hg*4096;        // + c*8192 per chunk
    int tr = tid >> 2, tq = tid & 3;               // A loader mapping (tid<256)

    auto load_chunk = [&](int c, int buf) {
        char* Ab = smc + buf*EAB;
        char* Bb = smc + EBBASE + buf*EBB;
        if (tid < 256)
            cp_async16(Ab + tr*80 + tq*16,
                       g_Ec + (i0 + tr)*128 + (size_t)c*16 + tq*4);
        const unsigned* bsrc = wbase + (size_t)c*8192;
        cp_async16(Bb + tid*16, bsrc + tid*4);
        cp_async16(Bb + (tid + 512)*16, bsrc + (tid + 512)*4);
        CP_COMMIT();
    };

    load_chunk(0, 0);
    load_chunk(1, 1);

    int buf = 0;
    #pragma unroll 1
    for (int c = 0; c < 8; c++) {
        if (c == 7) { CP_WAIT0(); } else { CP_WAIT1(); }
        __syncthreads();                 // chunk c resident in buf
        if (c < 6) {
            int nb = buf + 2; if (nb >= 3) nb -= 3;
            load_chunk(c + 2, nb);
        }
        const unsigned* Au = (const unsigned*)(smc + buf*EAB);
        const unsigned* Bu = (const unsigned*)(smc + EBBASE + buf*EBB);
        #pragma unroll
        for (int step = 0; step < 2; step++) {
            unsigned a[2][4];
            #pragma unroll
            for (int mi = 0; mi < 2; mi++) {
                int r = rh*32 + mi*16 + g;
                a[mi][0] = Au[r*EAW + step*8 + tig];
                a[mi][1] = Au[(r+8)*EAW + step*8 + tig];
                a[mi][2] = Au[r*EAW + step*8 + tig + 4];
                a[mi][3] = Au[(r+8)*EAW + step*8 + tig + 4];
            }
            unsigned br[8];
            const uint4* bs = (const uint4*)Bu + ((cw*2 + step) << 6);
            *(uint4*)(br + 0) = bs[lane];
            *(uint4*)(br + 4) = bs[32 + lane];
            #pragma unroll
            for (int nt = 0; nt < 4; nt++) {
                mma_bf16(acc[0][nt], a[0], br[2*nt], br[2*nt + 1]);
                mma_bf16(acc[1][nt], a[1], br[2*nt], br[2*nt + 1]);
            }
        }
        buf++; if (buf == 3) buf = 0;
    }
    __syncthreads();     // all MMA-LDS done before epilogue reuses smem

    // ---- epilogue: G warps stage sigmoid(G+beg) in fragment order ----
    float* Gs = sm;
    if (cw >= 4) {
        int gw = rh*4 + (cw - 4);
        float* dst = Gs + gw*1152 + lane*36;
        int cb0 = hg*128 + (cw - 4)*32;
        #pragma unroll
        for (int mi = 0; mi < 2; mi++)
            #pragma unroll
            for (int nt = 0; nt < 4; nt++) {
                int cc = cb0 + nt*8 + tig*2;
                float b0 = sbeg[cc], b1 = sbeg[cc + 1];
                float4 v;
                v.x = 1.f / (1.f + __expf(-(acc[mi][nt][0] + b0)));
                v.y = 1.f / (1.f + __expf(-(acc[mi][nt][1] + b1)));
                v.z = 1.f / (1.f + __expf(-(acc[mi][nt][2] + b0)));
                v.w = 1.f / (1.f + __expf(-(acc[mi][nt][3] + b1)));
                *(float4*)(dst + (mi*4 + nt)*4) = v;
            }
    }
    __syncthreads();

    // ---- P warps: gated product + tig-group reduction + scatter ----
    if (cw < 4) {
        int head = hg*4 + cw;
        const float* src = Gs + (rh*4 + cw)*1152 + lane*36;
        int cb0 = hg*128 + cw*32;
        float s[4] = {0.f, 0.f, 0.f, 0.f};     // [mi*2 + rowhalf]
        #pragma unroll
        for (int mi = 0; mi < 2; mi++)
            #pragma unroll
            for (int nt = 0; nt < 4; nt++) {
                int cc = cb0 + nt*8 + tig*2;
                float b0 = sbep[cc], b1 = sbep[cc + 1];
                float4 gv = *(const float4*)(src + (mi*4 + nt)*4);
                s[mi*2+0] += (acc[mi][nt][0] + b0)*gv.x + (acc[mi][nt][1] + b1)*gv.y;
                s[mi*2+1] += (acc[mi][nt][2] + b0)*gv.z + (acc[mi][nt][3] + b1)*gv.w;
            }
        #pragma unroll
        for (int o = 1; o < 4; o <<= 1) {
            #pragma unroll
            for (int j = 0; j < 4; j++) s[j] += __shfl_xor_sync(0xffffffffu, s[j], o);
        }
        if (tig == 0) {
            #pragma unroll
            for (int mi = 0; mi < 2; mi++)
                #pragma unroll
                for (int rr = 0; rr < 2; rr++) {
                    int r = rh*32 + mi*16 + g + rr*8;
                    size_t i = i0 + r;
                    int m = (int)(i & 255), n = (int)((i >> 8) & 255), b = (int)(i >> 16);
                    g_eattn[(((size_t)(b*NH + head)*NN + n)*NN) + m] = s[mi*2 + rr];
                }
        }
    }
}

// ---------------- fused attention: scores + bias + mask + softmax + attn@V ----------------
#define AKS 264
#define AVS 36
#define AQS 33
#define ATT_SMEM ((32*AKS + 256*AVS + 32*AQS + 32*AKS) * 4)

__global__ __launch_bounds__(256, 1)
void attention_kernel(const int* __restrict__ adj)
{
    extern __shared__ float smf[];
    float* Kt = smf;
    float* Vs = Kt + 32*AKS;
    float* Qs = Vs + 256*AVS;
    float* Ps = Qs + 32*AQS;

    int bid = blockIdx.x;
    int nb = bid & 7, h = (bid >> 3) & 7, b = bid >> 6;
    int n0 = nb * 32;
    int tid = threadIdx.x;

    const float* kbase = g_k + (size_t)(b*NN)*HIDD + h*DH;
    const float* vbase = g_v + (size_t)(b*NN)*HIDD + h*DH;
    #pragma unroll
    for (int it = 0; it < 32; it++) {
        int idx = tid + it*256;
        int m = idx >> 5, d = idx & 31;
        float kv = kbase[(size_t)m*HIDD + d];
        float vv = vbase[(size_t)m*HIDD + d];
        Kt[d*AKS + m] = kv;
        Vs[m*AVS + d] = vv;
    }
    #pragma unroll
    for (int it = 0; it < 4; it++) {
        int idx = tid + it*256;
        int r = idx >> 5, d = idx & 31;
        Qs[r*AQS + d] = g_q[(size_t)(b*NN + n0 + r)*HIDD + h*DH + d];
    }
    __syncthreads();

    int r = tid >> 3, cg = tid & 7;

    float acc[8][4];
    #pragma unroll
    for (int c = 0; c < 8; c++)
        #pragma unroll
        for (int j = 0; j < 4; j++) acc[c][j] = 0.f;

    #pragma unroll
    for (int d = 0; d < 32; d++) {
        float qd = Qs[r*AQS + d];
        const float* krow = Kt + d*AKS + cg*4;
        #pragma unroll
        for (int c = 0; c < 8; c++) {
            float4 kv = *(const float4*)(krow + c*32);
            acc[c][0] = fmaf(qd, kv.x, acc[c][0]);
            acc[c][1] = fmaf(qd, kv.y, acc[c][1]);
            acc[c][2] = fmaf(qd, kv.z, acc[c][2]);
            acc[c][3] = fmaf(qd, kv.w, acc[c][3]);
        }
    }

    size_t rowbase = ((size_t)(b*NH + h)*NN + (n0 + r)) * NN;
    const float* erow = g_eattn + rowbase;
    const int*   arow = adj + (size_t)(b*NN + n0 + r)*NN;

    const float scale = 0.17677669529663687f;
    float mx = -1e30f;
    #pragma unroll
    for (int c = 0; c < 8; c++) {
        int m0 = cg*4 + c*32;
        float4 ev = *(const float4*)(erow + m0);
        int4   av = *(const int4*)(arow + m0);
        acc[c][0] = (av.x == 0) ? -1e9f : fmaf(acc[c][0], scale, ev.x);
        acc[c][1] = (av.y == 0) ? -1e9f : fmaf(acc[c][1], scale, ev.y);
        acc[c][2] = (av.z == 0) ? -1e9f : fmaf(acc[c][2], scale, ev.z);
        acc[c][3] = (av.w == 0) ? -1e9f : fmaf(acc[c][3], scale, ev.w);
        #pragma unroll
        for (int j = 0; j < 4; j++) mx = fmaxf(mx, acc[c][j]);
    }
    #pragma unroll
    for (int o = 1; o < 8; o <<= 1) mx = fmaxf(mx, __shfl_xor_sync(0xffffffffu, mx, o));

    float sum = 0.f;
    #pragma unroll
    for (int c = 0; c < 8; c++)
        #pragma unroll
        for (int j = 0; j < 4; j++) {
            acc[c][j] = __expf(acc[c][j] - mx);
            sum += acc[c][j];
        }
    #pragma unroll
    for (int o = 1; o < 8; o <<= 1) sum += __shfl_xor_sync(0xffffffffu, sum, o);
    float inv = 1.f / sum;

    float* psrow = Ps + r*AKS;
    float* grow  = g_scores + rowbase;
    #pragma unroll
    for (int c = 0; c < 8; c++) {
        int m0 = cg*4 + c*32;
        float4 p;
        p.x = acc[c][0] * inv; p.y = acc[c][1] * inv;
        p.z = acc[c][2] * inv; p.w = acc[c][3] * inv;
        *(float4*)(psrow + m0) = p;
        *(float4*)(grow + m0)  = p;
    }
    __syncwarp();

    float o0 = 0.f, o1 = 0.f, o2 = 0.f, o3 = 0.f;
    #pragma unroll 8
    for (int m = 0; m < 256; m++) {
        float p = psrow[m];
        float4 vv = *(const float4*)(Vs + m*AVS + cg*4);
        o0 = fmaf(p, vv.x, o0);
        o1 = fmaf(p, vv.y, o1);
        o2 = fmaf(p, vv.z, o2);
        o3 = fmaf(p, vv.w, o3);
    }
    float4 ov = {o0, o1, o2, o3};
    *(float4*)(g_ao + (size_t)(b*NN + n0 + r)*HIDD + h*DH + cg*4) = ov;
}

// ---------------- generic fp32 GEMM body: 32x64 tile, BK=32 ----------------
__device__ __forceinline__ void gemm_body(const float* __restrict__ A, const float* __restrict__ W,
                                          const float* __restrict__ bias, float* __restrict__ C,
                                          int M, int Nc, int K, int bx, int by)
{
    __shared__ float As[32][33];
    __shared__ float Ws[32][64];
    int tid = threadIdx.x;
    int r0 = by * 32, c0 = bx * 64;
    int ty = tid >> 4, tx = tid & 15;
    float acc[2][4] = {};

    for (int kc = 0; kc < K; kc += 32) {
        {
            int r = tid >> 3, c4 = tid & 7;
            float4 v = *(const float4*)(A + (size_t)(r0 + r)*K + kc + c4*4);
            As[c4*4+0][r] = v.x; As[c4*4+1][r] = v.y;
            As[c4*4+2][r] = v.z; As[c4*4+3][r] = v.w;
        }
        #pragma unroll
        for (int it = 0; it < 2; it++) {
            int j = tid + it*256;
            int rr = j >> 4, c4 = j & 15;
            *(float4*)(&Ws[rr][c4*4]) = *(const float4*)(W + (size_t)(kc + rr)*Nc + c0 + c4*4);
        }
        __syncthreads();
        #pragma unroll
        for (int k = 0; k < 32; k++) {
            float a0 = As[k][ty*2], a1 = As[k][ty*2+1];
            float4 bv = *(float4*)(&Ws[k][tx*4]);
            acc[0][0] = fmaf(a0, bv.x, acc[0][0]);
            acc[0][1] = fmaf(a0, bv.y, acc[0][1]);
            acc[0][2] = fmaf(a0, bv.z, acc[0][2]);
            acc[0][3] = fmaf(a0, bv.w, acc[0][3]);
            acc[1][0] = fmaf(a1, bv.x, acc[1][0]);
            acc[1][1] = fmaf(a1, bv.y, acc[1][1]);
            acc[1][2] = fmaf(a1, bv.z, acc[1][2]);
            acc[1][3] = fmaf(a1, bv.w, acc[1][3]);
        }
        __syncthreads();
    }
    #pragma unroll
    for (int i = 0; i < 2; i++)
        #pragma unroll
        for (int j = 0; j < 4; j++) {
            int cc = c0 + tx*4 + j;
            float v = acc[i][j];
            if (bias) v += bias[cc];
            C[(size_t)(r0 + ty*2 + i)*Nc + cc] = v;
        }
}

__global__ __launch_bounds__(256)
void gemm_one_kernel(const float* __restrict__ A, const float* __restrict__ W,
                     const float* __restrict__ bias, float* __restrict__ C,
                     int M, int Nc, int K)
{
    gemm_body(A, W, bias, C, M, Nc, K, blockIdx.x, blockIdx.y);
}

__global__ __launch_bounds__(256)
void gemm_qkv_kernel(const float* __restrict__ A,
                     const float* __restrict__ Wq, const float* __restrict__ bq,
                     const float* __restrict__ Wk, const float* __restrict__ bk,
                     const float* __restrict__ Wv, const float* __restrict__ bv,
                     float* __restrict__ oq, float* __restrict__ ok, float* __restrict__ ov)
{
    int z = blockIdx.z;
    const float* W = (z == 0) ? Wq : (z == 1) ? Wk : Wv;
    const float* bb = (z == 0) ? bq : (z == 1) ? bk : bv;
    float* C = (z == 0) ? oq : (z == 1) ? ok : ov;
    gemm_body(A, W, bb, C, 512, 256, 256, blockIdx.x, blockIdx.y);
}

// ---------------- attn mean over heads ----------------
__global__ __launch_bounds__(256)
void attn_mean_kernel()
{
    int j = blockIdx.x * 256 + threadIdx.x;
    int b = j >> 16, nm = j & 65535;
    float s = 0.f;
    #pragma unroll
    for (int h = 0; h < NH; h++) s += g_scores[(((size_t)(b*NH + h)) << 16) + nm];
    g_amean[j] = s * 0.125f;
}

// ---------------- h_out = LN(residual + o)  (warp per row) ----------------
__global__ __launch_bounds__(256)
void ln_node_kernel(const float* __restrict__ g1, const float* __restrict__ b1,
                    float* __restrict__ out)
{
    int row = blockIdx.x * 8 + (threadIdx.x >> 5);
    int lane = threadIdx.x & 31;
    const float* ha = g_h + (size_t)row*256;
    const float* ta = g_tmp + (size_t)row*256;
    float4 a0 = *(const float4*)(ha + lane*4);
    float4 t0 = *(const float4*)(ta + lane*4);
    float4 a1 = *(const float4*)(ha + 128 + lane*4);
    float4 t1 = *(const float4*)(ta + 128 + lane*4);
    float x[8] = {a0.x+t0.x, a0.y+t0.y, a0.z+t0.z, a0.w+t0.w,
                  a1.x+t1.x, a1.y+t1.y, a1.z+t1.z, a1.w+t1.w};
    float s = 0.f;
    #pragma unroll
    for (int j = 0; j < 8; j++) s += x[j];
    float mean = warpSum(s) * (1.f/256.f);
    float vs = 0.f;
    #pragma unroll
    for (int j = 0; j < 8; j++) { float d = x[j] - mean; vs += d*d; }
    float inv = rsqrtf(warpSum(vs) * (1.f/256.f) + LN_EPS);
    float* o = out + (size_t)row*256;
    #pragma unroll
    for (int j = 0; j < 8; j++) {
        int c = (j < 4) ? (lane*4 + j) : (128 + lane*4 + j - 4);
        o[c] = (x[j] - mean) * inv * g1[c] + b1[c];
    }
}

// ---------------- edge_out = LN(E + amean*0.5*(P_n + P_m) + beo)  (warp per row) ----------------
__global__ __launch_bounds__(256)
void edge_out_kernel(const float* __restrict__ E, const float* __restrict__ beo,
                     const float* __restrict__ g2, const float* __restrict__ b2,
                     float* __restrict__ out)
{
    size_t i = (size_t)blockIdx.x * 8 + (threadIdx.x >> 5);
    int lane = threadIdx.x & 31;
    int m = (int)(i & 255), n = (int)((i >> 8) & 255), b = (int)(i >> 16);
    float am = g_amean[i] * 0.5f;
    const float* Er = E + i*256;
    const float* Pn = g_P + (size_t)(b*NN + n)*256;
    const float* Pm = g_P + (size_t)(b*NN + m)*256;

    float x[8];
    #pragma unroll
    for (int half = 0; half < 2; half++) {
        int c = half*128 + lane*4;
        float4 e  = *(const float4*)(Er + c);
        float4 pn = *(const float4*)(Pn + c);
        float4 pm = *(const float4*)(Pm + c);
        float4 bo = *(const float4*)(beo + c);
        x[half*4+0] = e.x + am*(pn.x + pm.x) + bo.x;
        x[half*4+1] = e.y + am*(pn.y + pm.y) + bo.y;
        x[half*4+2] = e.z + am*(pn.z + pm.z) + bo.z;
        x[half*4+3] = e.w + am*(pn.w + pm.w) + bo.w;
    }
    float s = 0.f;
    #pragma unroll
    for (int j = 0; j < 8; j++) s += x[j];
    float mean = warpSum(s) * (1.f/256.f);
    float vs = 0.f;
    #pragma unroll
    for (int j = 0; j < 8; j++) { float d = x[j] - mean; vs += d*d; }
    float inv = rsqrtf(warpSum(vs) * (1.f/256.f) + LN_EPS);
    float* o = out + i*256;
    #pragma unroll
    for (int half = 0; half < 2; half++) {
        int c = half*128 + lane*4;
        float4 gg = *(const float4*)(g2 + c);
        float4 bb = *(const float4*)(b2 + c);
        float4 r;
        r.x = (x[half*4+0] - mean) * inv * gg.x + bb.x;
        r.y = (x[half*4+1] - mean) * inv * gg.y + bb.y;
        r.z = (x[half*4+2] - mean) * inv * gg.z + bb.z;
        r.w = (x[half*4+3] - mean) * inv * gg.w + bb.w;
        *(float4*)(o + c) = r;
    }
}

// ---------------- launch ----------------
extern "C" void kernel_launch(void* const* d_in, const int* in_sizes, int n_in,
                              void* d_out, int out_size)
{
    const float* node = (const float*)d_in[0];
    const float* edge = (const float*)d_in[1];
    const int*   adj  = (const int*)  d_in[2];
    const float* Wn  = (const float*)d_in[3];  const float* bn  = (const float*)d_in[4];
    const float* Wq  = (const float*)d_in[5];  const float* bq  = (const float*)d_in[6];
    const float* Wk  = (const float*)d_in[7];  const float* bk  = (const float*)d_in[8];
    const float* Wv  = (const float*)d_in[9];  const float* bv  = (const float*)d_in[10];
    const float* Wep = (const float*)d_in[11]; const float* bep = (const float*)d_in[12];
    const float* Weg = (const float*)d_in[13]; const float* beg = (const float*)d_in[14];
    const float* Wo  = (const float*)d_in[15]; const float* bo  = (const float*)d_in[16];
    const float* Weo = (const float*)d_in[17]; const float* beo = (const float*)d_in[18];
    const float* g1  = (const float*)d_in[19]; const float* b1  = (const float*)d_in[20];
    const float* g2  = (const float*)d_in[21]; const float* b2  = (const float*)d_in[22];

    float* out   = (float*)d_out;
    float* h_out = out;
    float* e_out = out + (size_t)BB*NN*HIDD;

    float *ph, *pq, *pk, *pv, *pao, *ptmp, *pP;
    cudaGetSymbolAddress((void**)&ph,   g_h);
    cudaGetSymbolAddress((void**)&pq,   g_q);
    cudaGetSymbolAddress((void**)&pk,   g_k);
    cudaGetSymbolAddress((void**)&pv,   g_v);
    cudaGetSymbolAddress((void**)&pao,  g_ao);
    cudaGetSymbolAddress((void**)&ptmp, g_tmp);
    cudaGetSymbolAddress((void**)&pP,   g_P);

    cudaFuncSetAttribute(edge_attn_mma_kernel,
                         cudaFuncAttributeMaxDynamicSharedMemorySize, EDGE_SMEM);
    cudaFuncSetAttribute(attention_kernel,
                         cudaFuncAttributeMaxDynamicSharedMemorySize, ATT_SMEM);

    // E + weight pre-converts, then node projection
    cvt_e_kernel<<<32768, 256>>>(edge);
    cvt_w_kernel<<<256, 256>>>(Wep, Weg);
    gemm_one_kernel<<<dim3(4, 16), 256>>>(node, Wn, bn, ph, 512, 256, 128);

    // QKV in one launch
    gemm_qkv_kernel<<<dim3(4, 16, 3), 256>>>(ph, Wq, bq, Wk, bk, Wv, bv, pq, pk, pv);

    // edge bias (tensor cores, head-group split, fully async operand feed)
    edge_attn_mma_kernel<<<dim3((BB*NN*NN)/64, 2), 512, EDGE_SMEM>>>(bep, beg);
    attention_kernel<<<BB*NH*8, 256, ATT_SMEM>>>(adj);

    // mean over heads (for edge update)
    attn_mean_kernel<<<(BB*NN*NN)/256, 256>>>();

    // out-proj + node LN
    gemm_one_kernel<<<dim3(4, 16), 256>>>(pao, Wo, bo, ptmp, 512, 256, 256);
    ln_node_kernel<<<(BB*NN)/8, 256>>>(g1, b1, h_out);

    // P = h_out @ Weo, then fused edge output LN
    gemm_one_kernel<<<dim3(4, 16), 256>>>(h_out, Weo, (const float*)nullptr, pP, 512, 256, 256);
    edge_out_kernel<<<(BB*NN*NN)/8, 256>>>(edge, beo, g2, b2, e_out);
}